// round 11
// baseline (speedup 1.0000x reference)
#include <cuda_runtime.h>
#include <cstdint>
#include <cfloat>

// RandomProjectionQuantizer (R10 — FLOAT OUTPUT):
//   xp = x @ P    (normalization skipped: positive row scale preserves argmax)
//   out[i] = (float) argmax_j xp_i . CB_j
//
// Root cause of six rounds of rel_err == 1.000000e+00: the harness compares
// d_out as float32; integer index writes are denormals (~1e-41 ~= 0) under a
// float view, giving ||0-ref||/||ref|| = 1.0 exactly, invariant to algorithm.
// Fix: write indices as float values (<= 8191, exactly representable).
//
// Shapes derived from in_sizes/out_size (element counts), bounds-guarded.

#define ROWS_PER_BLK 128
#define THREADS      256
#define CHUNK        256   // codes staged per smem pass

template <int CBD>
union SMemT {
    struct {
        __align__(16) float xs[ROWS_PER_BLK][33];
        __align__(16) float Ps[32][CBD];
    } p1;
    __align__(16) float cbs[CHUNK][CBD];
    struct { float sv[THREADS]; int si[THREADS]; } p3;
};

template <int CBD>
__global__ __launch_bounds__(THREADS)
void rpq_kernel(const float* __restrict__ x, const float* __restrict__ P,
                const float* __restrict__ CB, float* __restrict__ out,
                int N, int D, int V) {
    __shared__ SMemT<CBD> sm;

    const int t    = threadIdx.x;
    const int rl   = t & (ROWS_PER_BLK - 1);
    const int half = t >> 7;                  // 0: codes [c0,c0+128); 1: [c0+128,c0+256)
    const int row0 = blockIdx.x * ROWS_PER_BLK;

    // ---------------- Phase 1: projection (acc[CBD] in registers) --------------
    float acc[CBD];
#pragma unroll
    for (int i = 0; i < CBD; i++) acc[i] = 0.0f;

    const int nkc = (D + 31) >> 5;
    for (int kc = 0; kc < nkc; kc++) {
#pragma unroll
        for (int q = t; q < ROWS_PER_BLK * 32; q += THREADS) {
            int r = q >> 5, c = q & 31;
            int row = row0 + r, d = kc * 32 + c;
            sm.p1.xs[r][c] = (row < N && d < D) ? x[(long long)row * D + d] : 0.0f;
        }
#pragma unroll
        for (int q = t; q < 32 * CBD; q += THREADS) {
            int k = q / CBD, i = q % CBD;
            int d = kc * 32 + k;
            sm.p1.Ps[k][i] = (d < D) ? P[(long long)d * CBD + i] : 0.0f;
        }
        __syncthreads();

#pragma unroll 4
        for (int k = 0; k < 32; k++) {
            float xv = sm.p1.xs[rl][k];                         // stride-33: conflict-free
            const float4* pr = (const float4*)&sm.p1.Ps[k][0];  // warp-uniform: broadcast
#pragma unroll
            for (int i4 = 0; i4 < CBD / 4; i4++) {
                float4 p = pr[i4];
                acc[4 * i4]     = fmaf(xv, p.x, acc[4 * i4]);
                acc[4 * i4 + 1] = fmaf(xv, p.y, acc[4 * i4 + 1]);
                acc[4 * i4 + 2] = fmaf(xv, p.z, acc[4 * i4 + 2]);
                acc[4 * i4 + 3] = fmaf(xv, p.w, acc[4 * i4 + 3]);
            }
        }
        __syncthreads();
    }

    // ---------------- Phase 2: argmax over V codes (half-split) ----------------
    float best = -FLT_MAX;
    int   bi   = 0x7FFFFFFF;   // sentinel: larger than any real index

    for (int c0 = 0; c0 < V; c0 += CHUNK) {
        const int cnt = (V - c0 < CHUNK) ? (V - c0) : CHUNK;
#pragma unroll
        for (int q = t; q < CHUNK * CBD; q += THREADS) {
            int j = q / CBD, i = q % CBD;
            sm.cbs[j][i] = (j < cnt) ? CB[(long long)(c0 + j) * CBD + i] : 0.0f;
        }
        __syncthreads();

        const int jbase = half * (CHUNK / 2);
#pragma unroll 2
        for (int jj = 0; jj < CHUNK / 2; jj++) {
            const int j = jbase + jj;                        // warp-uniform -> broadcast
            const float4* cb = (const float4*)&sm.cbs[j][0];
            float s0 = 0.0f, s1 = 0.0f, s2 = 0.0f, s3 = 0.0f;
#pragma unroll
            for (int i4 = 0; i4 < CBD / 4; i4++) {
                float4 c = cb[i4];
                s0 = fmaf(acc[4 * i4],     c.x, s0);
                s1 = fmaf(acc[4 * i4 + 1], c.y, s1);
                s2 = fmaf(acc[4 * i4 + 2], c.z, s2);
                s3 = fmaf(acc[4 * i4 + 3], c.w, s3);
            }
            float s = (s0 + s1) + (s2 + s3);
            // strict >: keeps FIRST max within this half's ascending index set
            if (c0 + j < V && s > best) { best = s; bi = c0 + j; }
        }
        __syncthreads();
    }

    // -------- Phase 3: combine halves (tie -> smaller global index), write float
    sm.p3.sv[t] = best;
    sm.p3.si[t] = bi;
    __syncthreads();

    if (t < ROWS_PER_BLK) {
        int row = row0 + t;
        if (row < N) {
            float slo = sm.p3.sv[t], shi = sm.p3.sv[t + 128];
            int   ilo = sm.p3.si[t], ihi = sm.p3.si[t + 128];
            // jnp.argmax = first occurrence of max over GLOBAL index order;
            // halves interleave, so ties must resolve to the smaller index.
            int win = (shi > slo || (shi == slo && ihi < ilo)) ? ihi : ilo;
            out[row] = (float)win;
        }
    }
}

// Generic fallback for unusual cbd (<=64). Correctness over speed.
__global__ void rpq_generic(const float* __restrict__ x, const float* __restrict__ P,
                            const float* __restrict__ CB, float* __restrict__ out,
                            int N, int D, int V, int cbd) {
    int row = blockIdx.x * blockDim.x + threadIdx.x;
    if (row >= N) return;
    float acc[64];
    for (int i = 0; i < cbd; i++) acc[i] = 0.0f;
    for (int d = 0; d < D; d++) {
        float xv = x[(long long)row * D + d];
        for (int i = 0; i < cbd; i++) acc[i] = fmaf(xv, P[(long long)d * cbd + i], acc[i]);
    }
    float best = -FLT_MAX; int bi = 0;
    for (int j = 0; j < V; j++) {
        float s = 0.0f;
        for (int i = 0; i < cbd; i++) s = fmaf(acc[i], CB[(long long)j * cbd + i], s);
        if (s > best) { best = s; bi = j; }   // strict >: first max
    }
    out[row] = (float)bi;
}

// ============================================================================
extern "C" void kernel_launch(void* const* d_in, const int* in_sizes, int n_in,
                              void* d_out, int out_size) {
    const float* x  = (const float*)d_in[0];
    const float* P  = (n_in > 1) ? (const float*)d_in[1] : nullptr;
    const float* CB = (n_in > 2) ? (const float*)d_in[2] : nullptr;
    long long N = out_size, D = 512, CBD = 16, V = 8192;

    if (n_in >= 3 && out_size > 0) {
        // x = largest input, P = smallest, CB = middle (unique sizes).
        int order[3] = {0, 1, 2};
        for (int a = 0; a < 2; a++)
            for (int b = a + 1; b < 3; b++)
                if ((long long)in_sizes[order[b]] > (long long)in_sizes[order[a]]) {
                    int tmp = order[a]; order[a] = order[b]; order[b] = tmp;
                }
        long long sx = in_sizes[order[0]];
        long long sc = in_sizes[order[1]];
        long long sp = in_sizes[order[2]];

        if (sx % N == 0) {
            long long d = sx / N;
            if (d > 0 && sp % d == 0) {
                long long cbd = sp / d;
                if (cbd > 0 && cbd <= 64 && sc % cbd == 0) {
                    long long v = sc / cbd;
                    if (v > 0 && d * cbd == sp && v * cbd == sc && N * d == sx) {
                        D = d; CBD = cbd; V = v;
                        x  = (const float*)d_in[order[0]];
                        CB = (const float*)d_in[order[1]];
                        P  = (const float*)d_in[order[2]];
                    }
                }
            }
        }
    }

    float* out = (float*)d_out;
    int Ni = (int)N, Di = (int)D, Vi = (int)V;
    int NB = (Ni + ROWS_PER_BLK - 1) / ROWS_PER_BLK;

    if      (CBD == 16) rpq_kernel<16><<<NB, THREADS>>>(x, P, CB, out, Ni, Di, Vi);
    else if (CBD == 8)  rpq_kernel<8> <<<NB, THREADS>>>(x, P, CB, out, Ni, Di, Vi);
    else if (CBD == 32) rpq_kernel<32><<<NB, THREADS>>>(x, P, CB, out, Ni, Di, Vi);
    else if (CBD == 4)  rpq_kernel<4> <<<NB, THREADS>>>(x, P, CB, out, Ni, Di, Vi);
    else rpq_generic<<<(Ni + 255) / 256, 256>>>(x, P, CB, out, Ni, Di, Vi, (int)CBD);
}

// round 12
// speedup vs baseline: 1.8993x; 1.8993x over previous
#include <cuda_runtime.h>
#include <cstdint>
#include <cfloat>

// RandomProjectionQuantizer (R11): split-K + FFMA2 (f32x2) scoring.
//   xp = x @ P    (normalization skipped: positive row scale preserves argmax)
//   out[i] = (float) argmax_j xp_i . CB_j      <- FLOAT output (R10 root cause)
//
// Fast path (CBD=16, N%256==0, V%256==0, D%32==0, N<=16384, V<=8192):
//   K1 proj  -> g_xp2 pair-interleaved (u64 k = (row_even dim k, row_odd dim k))
//   K2 split-K argmax partials: grid (rowpairs/256, 32 splits) = 1024 CTAs,
//      each thread scores its ROW PAIR with fma.rn.f32x2 (2 FMA/issue)
//   K3 reduce 32 partials/row (ascending splits + strict > = first-max), float out
// Fallback: R10 fused kernel (proven correct) for any other shape.

#define ROWS_PER_BLK 128
#define THREADS      256
#define CHUNK        256
#define SPLITS       32
#define MAXN         16384
#define MAXV         8192

// ---------------- scratch ----------------
__device__ __align__(16) float g_xp2[MAXN * 16];        // 1 MB pair-interleaved
__device__ float g_pval[SPLITS * MAXN];                 // 2 MB
__device__ int   g_pidx[SPLITS * MAXN];                 // 2 MB

// ---------------- f32x2 helpers ----------------
__device__ __forceinline__ unsigned long long splat2(float x) {
    unsigned long long r; unsigned int b = __float_as_uint(x);
    asm("mov.b64 %0, {%1, %1};" : "=l"(r) : "r"(b));
    return r;
}
__device__ __forceinline__ unsigned long long fma2(unsigned long long a,
                                                   unsigned long long b,
                                                   unsigned long long c) {
    unsigned long long d;
    asm("fma.rn.f32x2 %0, %1, %2, %3;" : "=l"(d) : "l"(a), "l"(b), "l"(c));
    return d;
}
__device__ __forceinline__ unsigned long long add2(unsigned long long a,
                                                   unsigned long long b) {
    unsigned long long d;
    asm("add.rn.f32x2 %0, %1, %2;" : "=l"(d) : "l"(a), "l"(b));
    return d;
}

// ============================================================================
// K1: projection, one row per thread, output pair-interleaved into g_xp2.
// ============================================================================
__global__ __launch_bounds__(128)
void proj_pairs(const float* __restrict__ x, const float* __restrict__ P,
                int N, int D) {
    __shared__ float xs[128][33];
    __shared__ __align__(16) float Ps[32][16];

    const int t = threadIdx.x;
    const int row0 = blockIdx.x * 128;

    float acc[16];
#pragma unroll
    for (int i = 0; i < 16; i++) acc[i] = 0.0f;

    const int nkc = D >> 5;                       // D % 32 == 0 guaranteed
    for (int kc = 0; kc < nkc; kc++) {
#pragma unroll
        for (int q = t; q < 128 * 32; q += 128) {
            int r = q >> 5, c = q & 31;
            xs[r][c] = x[(long long)(row0 + r) * D + kc * 32 + c];
        }
#pragma unroll
        for (int q = t; q < 32 * 16; q += 128) {
            int k = q >> 4, i = q & 15;
            Ps[k][i] = P[(long long)(kc * 32 + k) * 16 + i];
        }
        __syncthreads();

#pragma unroll 4
        for (int k = 0; k < 32; k++) {
            float xv = xs[t][k];
            const float4* pr = (const float4*)&Ps[k][0];
#pragma unroll
            for (int i4 = 0; i4 < 4; i4++) {
                float4 p = pr[i4];
                acc[4 * i4]     = fmaf(xv, p.x, acc[4 * i4]);
                acc[4 * i4 + 1] = fmaf(xv, p.y, acc[4 * i4 + 1]);
                acc[4 * i4 + 2] = fmaf(xv, p.z, acc[4 * i4 + 2]);
                acc[4 * i4 + 3] = fmaf(xv, p.w, acc[4 * i4 + 3]);
            }
        }
        __syncthreads();
    }

    // pair-interleave: g_xp2[(row>>1)*32 + 2k + (row&1)] = xp[row][k]
    const int row = row0 + t;
    float* dst = g_xp2 + (row >> 1) * 32 + (row & 1);
#pragma unroll
    for (int k = 0; k < 16; k++) dst[2 * k] = acc[k];
}

// ============================================================================
// K2: split-K argmax partials with FFMA2. grid = (rowpairs/256, SPLITS).
// ============================================================================
__global__ __launch_bounds__(THREADS)
void argmax_partial(const float* __restrict__ CB, int N, int V) {
    __shared__ __align__(16) unsigned long long cbs[CHUNK][16];   // 32 KB

    const int t = threadIdx.x;
    const int code0 = blockIdx.y * CHUNK;

    // stage CB chunk, value splatted into both f32x2 lanes
#pragma unroll 4
    for (int q = t; q < CHUNK * 16; q += THREADS) {
        float c = CB[(long long)(code0 + (q >> 4)) * 16 + (q & 15)];
        cbs[q >> 4][q & 15] = splat2(c);
    }

    // this thread's row pair: u64 k = (row_even dim k, row_odd dim k)
    const int rp = blockIdx.x * THREADS + t;
    const ulonglong2* xg = (const ulonglong2*)(g_xp2 + (long long)rp * 32);
    unsigned long long xp[16];
#pragma unroll
    for (int i = 0; i < 8; i++) { ulonglong2 v = xg[i]; xp[2 * i] = v.x; xp[2 * i + 1] = v.y; }

    __syncthreads();

    float best0 = -FLT_MAX, best1 = -FLT_MAX;
    int idx0 = 0, idx1 = 0;

#pragma unroll 2
    for (int j = 0; j < CHUNK; j++) {
        const ulonglong2* cp = (const ulonglong2*)&cbs[j][0];     // broadcast LDS.128
        unsigned long long a = 0ULL, b = 0ULL;                    // 2 chains for ILP
#pragma unroll
        for (int i = 0; i < 8; i++) {
            ulonglong2 c = cp[i];
            a = fma2(xp[2 * i],     c.x, a);
            b = fma2(xp[2 * i + 1], c.y, b);
        }
        union { unsigned long long u; float f[2]; } s; s.u = add2(a, b);
        if (s.f[0] > best0) { best0 = s.f[0]; idx0 = j; }         // strict >: first max
        if (s.f[1] > best1) { best1 = s.f[1]; idx1 = j; }
    }

    const long long off = (long long)blockIdx.y * N + (long long)rp * 2;
    g_pval[off]     = best0;  g_pidx[off]     = code0 + idx0;
    g_pval[off + 1] = best1;  g_pidx[off + 1] = code0 + idx1;
}

// ============================================================================
// K3: reduce SPLITS partials per row; ascending split + strict > = global
// first-max index. FLOAT output.
// ============================================================================
__global__ __launch_bounds__(256)
void argmax_reduce(float* __restrict__ out, int N, int nsplit) {
    const int row = blockIdx.x * 256 + threadIdx.x;
    if (row >= N) return;
    float best = -FLT_MAX;
    int bi = 0;
    for (int s = 0; s < nsplit; s++) {
        float v = g_pval[(long long)s * N + row];
        if (v > best) { best = v; bi = g_pidx[(long long)s * N + row]; }
    }
    out[row] = (float)bi;
}

// ============================================================================
// Fallback: R10 fused kernel (proven correct), CBD=16 instantiation + generic.
// ============================================================================
union SMemF {
    struct { __align__(16) float xs[128][33]; __align__(16) float Ps[32][16]; } p1;
    __align__(16) float cbs[CHUNK][16];
    struct { float sv[THREADS]; int si[THREADS]; } p3;
};

__global__ __launch_bounds__(THREADS)
void rpq_fused16(const float* __restrict__ x, const float* __restrict__ P,
                 const float* __restrict__ CB, float* __restrict__ out,
                 int N, int D, int V) {
    __shared__ SMemF sm;
    const int t = threadIdx.x;
    const int rl = t & 127;
    const int half = t >> 7;
    const int row0 = blockIdx.x * 128;

    float acc[16];
#pragma unroll
    for (int i = 0; i < 16; i++) acc[i] = 0.0f;

    const int nkc = (D + 31) >> 5;
    for (int kc = 0; kc < nkc; kc++) {
#pragma unroll
        for (int q = t; q < 128 * 32; q += THREADS) {
            int r = q >> 5, c = q & 31;
            int row = row0 + r, d = kc * 32 + c;
            sm.p1.xs[r][c] = (row < N && d < D) ? x[(long long)row * D + d] : 0.0f;
        }
#pragma unroll
        for (int q = t; q < 32 * 16; q += THREADS) {
            int k = q >> 4, i = q & 15;
            int d = kc * 32 + k;
            sm.p1.Ps[k][i] = (d < D) ? P[(long long)d * 16 + i] : 0.0f;
        }
        __syncthreads();
#pragma unroll 4
        for (int k = 0; k < 32; k++) {
            float xv = sm.p1.xs[rl][k];
            const float4* pr = (const float4*)&sm.p1.Ps[k][0];
#pragma unroll
            for (int i4 = 0; i4 < 4; i4++) {
                float4 p = pr[i4];
                acc[4 * i4]     = fmaf(xv, p.x, acc[4 * i4]);
                acc[4 * i4 + 1] = fmaf(xv, p.y, acc[4 * i4 + 1]);
                acc[4 * i4 + 2] = fmaf(xv, p.z, acc[4 * i4 + 2]);
                acc[4 * i4 + 3] = fmaf(xv, p.w, acc[4 * i4 + 3]);
            }
        }
        __syncthreads();
    }

    float best = -FLT_MAX; int bi = 0x7FFFFFFF;
    for (int c0 = 0; c0 < V; c0 += CHUNK) {
        const int cnt = (V - c0 < CHUNK) ? (V - c0) : CHUNK;
#pragma unroll
        for (int q = t; q < CHUNK * 16; q += THREADS) {
            int j = q >> 4, i = q & 15;
            sm.cbs[j][i] = (j < cnt) ? CB[(long long)(c0 + j) * 16 + i] : 0.0f;
        }
        __syncthreads();
        const int jbase = half * 128;
#pragma unroll 2
        for (int jj = 0; jj < 128; jj++) {
            const int j = jbase + jj;
            const float4* cb = (const float4*)&sm.cbs[j][0];
            float s0 = 0, s1 = 0, s2 = 0, s3 = 0;
#pragma unroll
            for (int i4 = 0; i4 < 4; i4++) {
                float4 c = cb[i4];
                s0 = fmaf(acc[4 * i4],     c.x, s0);
                s1 = fmaf(acc[4 * i4 + 1], c.y, s1);
                s2 = fmaf(acc[4 * i4 + 2], c.z, s2);
                s3 = fmaf(acc[4 * i4 + 3], c.w, s3);
            }
            float s = (s0 + s1) + (s2 + s3);
            if (c0 + j < V && s > best) { best = s; bi = c0 + j; }
        }
        __syncthreads();
    }

    sm.p3.sv[t] = best; sm.p3.si[t] = bi;
    __syncthreads();
    if (t < 128) {
        int row = row0 + t;
        if (row < N) {
            float slo = sm.p3.sv[t], shi = sm.p3.sv[t + 128];
            int   ilo = sm.p3.si[t], ihi = sm.p3.si[t + 128];
            int win = (shi > slo || (shi == slo && ihi < ilo)) ? ihi : ilo;
            out[row] = (float)win;
        }
    }
}

__global__ void rpq_generic(const float* __restrict__ x, const float* __restrict__ P,
                            const float* __restrict__ CB, float* __restrict__ out,
                            int N, int D, int V, int cbd) {
    int row = blockIdx.x * blockDim.x + threadIdx.x;
    if (row >= N) return;
    float acc[64];
    for (int i = 0; i < cbd; i++) acc[i] = 0.0f;
    for (int d = 0; d < D; d++) {
        float xv = x[(long long)row * D + d];
        for (int i = 0; i < cbd; i++) acc[i] = fmaf(xv, P[(long long)d * cbd + i], acc[i]);
    }
    float best = -FLT_MAX; int bi = 0;
    for (int j = 0; j < V; j++) {
        float s = 0.0f;
        for (int i = 0; i < cbd; i++) s = fmaf(acc[i], CB[(long long)j * cbd + i], s);
        if (s > best) { best = s; bi = j; }
    }
    out[row] = (float)bi;
}

// ============================================================================
extern "C" void kernel_launch(void* const* d_in, const int* in_sizes, int n_in,
                              void* d_out, int out_size) {
    const float* x  = (const float*)d_in[0];
    const float* P  = (n_in > 1) ? (const float*)d_in[1] : nullptr;
    const float* CB = (n_in > 2) ? (const float*)d_in[2] : nullptr;
    long long N = out_size, D = 512, CBD = 16, V = 8192;
    bool derived = false;

    if (n_in >= 3 && out_size > 0) {
        int order[3] = {0, 1, 2};
        for (int a = 0; a < 2; a++)
            for (int b = a + 1; b < 3; b++)
                if ((long long)in_sizes[order[b]] > (long long)in_sizes[order[a]]) {
                    int tmp = order[a]; order[a] = order[b]; order[b] = tmp;
                }
        long long sx = in_sizes[order[0]];
        long long sc = in_sizes[order[1]];
        long long sp = in_sizes[order[2]];
        if (sx % N == 0) {
            long long d = sx / N;
            if (d > 0 && sp % d == 0) {
                long long cbd = sp / d;
                if (cbd > 0 && cbd <= 64 && sc % cbd == 0) {
                    long long v = sc / cbd;
                    if (v > 0 && d * cbd == sp && v * cbd == sc && N * d == sx) {
                        D = d; CBD = cbd; V = v; derived = true;
                        x  = (const float*)d_in[order[0]];
                        CB = (const float*)d_in[order[1]];
                        P  = (const float*)d_in[order[2]];
                    }
                }
            }
        }
    }
    (void)derived;

    float* out = (float*)d_out;
    int Ni = (int)N, Di = (int)D, Vi = (int)V;

    const bool fast = (CBD == 16) && (Ni % 256 == 0) && (Vi % CHUNK == 0) &&
                      (Di % 32 == 0) && (Ni <= MAXN) && (Vi <= MAXV) &&
                      ((Vi / CHUNK) <= SPLITS) && (Vi >= CHUNK);

    if (fast) {
        const int nsplit    = Vi / CHUNK;            // 32 for template shape
        const int rowpairs  = Ni / 2;
        const int rowblocks = rowpairs / THREADS;    // Ni%512==0 when Ni%256==0 and pairs/256 int
        if (rowpairs % THREADS == 0) {
            proj_pairs<<<Ni / 128, 128>>>(x, P, Ni, Di);
            argmax_partial<<<dim3(rowblocks, nsplit), THREADS>>>(CB, Ni, Vi);
            argmax_reduce<<<(Ni + 255) / 256, 256>>>(out, Ni, nsplit);
            return;
        }
    }

    if (CBD == 16) {
        rpq_fused16<<<(Ni + 127) / 128, THREADS>>>(x, P, CB, out, Ni, Di, Vi);
    } else {
        rpq_generic<<<(Ni + 255) / 256, 256>>>(x, P, CB, out, Ni, Di, Vi, (int)CBD);
    }
}